// round 3
// baseline (speedup 1.0000x reference)
#include <cuda_runtime.h>
#include <cuda_bf16.h>
#include <cstdint>
#include <cstdio>

#define SEQ 2048
#define DIM 4096
#define NH 32
#define NKV 8
#define HD 128
#define KVD (NKV*HD)   // 1024

// Scratch (static __device__ allowed; cudaMalloc is not)
__device__ float g_q[SEQ * DIM];       // 32 MB
__device__ float g_k[SEQ * KVD];       // 8 MB
__device__ float g_v[SEQ * KVD];       // 8 MB
__device__ float g_attn[SEQ * DIM];    // 32 MB

__device__ __forceinline__ uint32_t f2tf(float f) {
    uint32_t u;
    asm("cvt.rna.tf32.f32 %0, %1;" : "=r"(u) : "f"(f));
    return u;
}

__device__ __forceinline__ void mma_tf32(float* d,
                                         uint32_t a0, uint32_t a1, uint32_t a2, uint32_t a3,
                                         uint32_t b0, uint32_t b1) {
    asm volatile(
        "mma.sync.aligned.m16n8k8.row.col.f32.tf32.tf32.f32 "
        "{%0,%1,%2,%3}, {%4,%5,%6,%7}, {%8,%9}, {%0,%1,%2,%3};"
        : "+f"(d[0]), "+f"(d[1]), "+f"(d[2]), "+f"(d[3])
        : "r"(a0), "r"(a1), "r"(a2), "r"(a3), "r"(b0), "r"(b1));
}

// ---------------------------------------------------------------------------
// GEMM: C[M,N] = A[M,K] @ B[N,K]^T   (both row-major, K contiguous)
// CTA tile 128x128, K-step 32, double-buffered smem, tf32 mma.
// ---------------------------------------------------------------------------
#define GS 36                        // smem stride in floats (4r+c % 32 -> conflict free frags)
#define GEMM_SMEM (4 * 128 * GS * 4) // 2 stages * (A + B) * 128*36 * 4B = 73728

__global__ void __launch_bounds__(256) gemm_nt_tf32(
    const float* __restrict__ A, const float* __restrict__ B,
    float* __restrict__ C, int N, int K)
{
    extern __shared__ uint32_t smem[];
    uint32_t* As = smem;               // [2][128*GS]
    uint32_t* Bs = smem + 2 * 128 * GS;

    const int tid  = threadIdx.x;
    const int warp = tid >> 5, lane = tid & 31;
    const int gid  = lane >> 2, tig = lane & 3;
    const int bm   = blockIdx.y, bn = blockIdx.x;
    const int wm   = warp >> 2, wn = warp & 3;     // 2 x 4 warp grid

    const float* Ab = A + (size_t)(bm * 128) * K;
    const float* Bb = B + (size_t)(bn * 128) * K;

    float acc[4][4][4];
#pragma unroll
    for (int i = 0; i < 4; i++)
#pragma unroll
        for (int j = 0; j < 4; j++)
#pragma unroll
            for (int q = 0; q < 4; q++) acc[i][j][q] = 0.f;

    int lr[4], lc[4];
#pragma unroll
    for (int i = 0; i < 4; i++) {
        int idx = tid + i * 256;       // 128 rows x 8 float4
        lr[i] = idx >> 3;
        lc[i] = (idx & 7) << 2;
    }

    // preload tile 0
#pragma unroll
    for (int i = 0; i < 4; i++) {
        float4 a = *(const float4*)(Ab + (size_t)lr[i] * K + lc[i]);
        float4 b = *(const float4*)(Bb + (size_t)lr[i] * K + lc[i]);
        uint32_t* da = &As[lr[i] * GS + lc[i]];
        da[0] = f2tf(a.x); da[1] = f2tf(a.y); da[2] = f2tf(a.z); da[3] = f2tf(a.w);
        uint32_t* db = &Bs[lr[i] * GS + lc[i]];
        db[0] = f2tf(b.x); db[1] = f2tf(b.y); db[2] = f2tf(b.z); db[3] = f2tf(b.w);
    }
    __syncthreads();

    const int nk = K / 32;
    for (int kt = 0; kt < nk; ++kt) {
        float4 pa[4], pb[4];
        if (kt + 1 < nk) {
#pragma unroll
            for (int i = 0; i < 4; i++) {
                pa[i] = *(const float4*)(Ab + (size_t)lr[i] * K + (kt + 1) * 32 + lc[i]);
                pb[i] = *(const float4*)(Bb + (size_t)lr[i] * K + (kt + 1) * 32 + lc[i]);
            }
        }
        const uint32_t* as = As + (kt & 1) * 128 * GS;
        const uint32_t* bs = Bs + (kt & 1) * 128 * GS;
#pragma unroll
        for (int ks = 0; ks < 4; ++ks) {
            const int kk = ks * 8;
            uint32_t af[4][4], bf[4][2];
#pragma unroll
            for (int mi = 0; mi < 4; ++mi) {
                int r = wm * 64 + mi * 16;
                af[mi][0] = as[(r + gid)     * GS + kk + tig];
                af[mi][1] = as[(r + gid + 8) * GS + kk + tig];
                af[mi][2] = as[(r + gid)     * GS + kk + tig + 4];
                af[mi][3] = as[(r + gid + 8) * GS + kk + tig + 4];
            }
#pragma unroll
            for (int ni = 0; ni < 4; ++ni) {
                int c = wn * 32 + ni * 8;
                bf[ni][0] = bs[(c + gid) * GS + kk + tig];
                bf[ni][1] = bs[(c + gid) * GS + kk + tig + 4];
            }
#pragma unroll
            for (int mi = 0; mi < 4; ++mi)
#pragma unroll
                for (int ni = 0; ni < 4; ++ni)
                    mma_tf32(acc[mi][ni], af[mi][0], af[mi][1], af[mi][2], af[mi][3],
                             bf[ni][0], bf[ni][1]);
        }
        if (kt + 1 < nk) {
            uint32_t* da = As + ((kt + 1) & 1) * 128 * GS;
            uint32_t* db = Bs + ((kt + 1) & 1) * 128 * GS;
#pragma unroll
            for (int i = 0; i < 4; i++) {
                uint32_t* pda = &da[lr[i] * GS + lc[i]];
                pda[0] = f2tf(pa[i].x); pda[1] = f2tf(pa[i].y);
                pda[2] = f2tf(pa[i].z); pda[3] = f2tf(pa[i].w);
                uint32_t* pdb = &db[lr[i] * GS + lc[i]];
                pdb[0] = f2tf(pb[i].x); pdb[1] = f2tf(pb[i].y);
                pdb[2] = f2tf(pb[i].z); pdb[3] = f2tf(pb[i].w);
            }
        }
        __syncthreads();
    }

    // epilogue
#pragma unroll
    for (int mi = 0; mi < 4; ++mi) {
        int r0 = bm * 128 + wm * 64 + mi * 16 + gid;
#pragma unroll
        for (int ni = 0; ni < 4; ++ni) {
            int c0 = bn * 128 + wn * 32 + ni * 8 + tig * 2;
            *(float2*)&C[(size_t)r0 * N + c0]       = make_float2(acc[mi][ni][0], acc[mi][ni][1]);
            *(float2*)&C[(size_t)(r0 + 8) * N + c0] = make_float2(acc[mi][ni][2], acc[mi][ni][3]);
        }
    }
}

// ---------------------------------------------------------------------------
// RoPE: pairs (2i, 2i+1) rotated by angle = pos * theta^(-i/64)
// ---------------------------------------------------------------------------
__global__ void rope_kernel(float* __restrict__ t, int H) {
    int idx = blockIdx.x * blockDim.x + threadIdx.x;
    int total = SEQ * H * 64;
    if (idx >= total) return;
    int i  = idx & 63;
    int tp = idx >> 6;
    int hh = tp % H;
    int s  = tp / H;

    // freq in fp32 (matches reference's fp32 freqs within ~1e-7 rel)
    float freq = exp2f(-(float)i * (18.931568569324174f / 64.0f));
    // angle product + range reduction in double to avoid fp32 catastrophic ulp at pos~2047
    double ang = (double)s * (double)freq;
    const double TWO_PI = 6.283185307179586476925286766559;
    ang -= TWO_PI * floor(ang / TWO_PI);
    float a = (float)ang;
    float sn, cs;
    sincosf(a, &sn, &cs);

    float* p = t + (size_t)s * (H * HD) + hh * HD + 2 * i;
    float x0 = p[0], x1 = p[1];
    p[0] = x0 * cs - x1 * sn;
    p[1] = x0 * sn + x1 * cs;
}

// ---------------------------------------------------------------------------
// Flash attention (causal, GQA group=4), tf32 mma.
// 1 CTA per (q-block of 128, head). 8 warps; warp owns 16 q rows.
// smem: Q[128][132], K[128][132] (reused as P), V[128][132]
// ---------------------------------------------------------------------------
#define AS 132
#define ATTN_SMEM (3 * 128 * AS * 4)   // 202752 B

__global__ void __launch_bounds__(256) attn_kernel() {
    extern __shared__ uint32_t sm[];
    uint32_t* Qs = sm;
    uint32_t* Ks = sm + 128 * AS;      // later reused for P
    uint32_t* Vs = sm + 2 * 128 * AS;

    const int qb  = blockIdx.x, h = blockIdx.y;
    const int kvh = h >> 2;
    const int q0  = qb * 128;
    const int tid = threadIdx.x;
    const int warp = tid >> 5, lane = tid & 31;
    const int gid = lane >> 2, tig = lane & 3;
    const int wr  = warp * 16;

    // load + convert Q tile
    for (int i = tid; i < 128 * 32; i += 256) {
        int r = i >> 5, c = (i & 31) << 2;
        float4 v = *(const float4*)(&g_q[(size_t)(q0 + r) * DIM + h * HD + c]);
        uint32_t* d = &Qs[r * AS + c];
        d[0] = f2tf(v.x); d[1] = f2tf(v.y); d[2] = f2tf(v.z); d[3] = f2tf(v.w);
    }

    float o[16][4];
#pragma unroll
    for (int i = 0; i < 16; i++)
#pragma unroll
        for (int j = 0; j < 4; j++) o[i][j] = 0.f;
    float m1 = -1e30f, m2 = -1e30f, l1 = 0.f, l2 = 0.f;

    for (int kb = 0; kb <= qb; ++kb) {
        __syncthreads();  // prior iteration's P/V reads done before overwrite
        for (int i = tid; i < 128 * 32; i += 256) {
            int r = i >> 5, c = (i & 31) << 2;
            float4 kv = *(const float4*)(&g_k[(size_t)(kb * 128 + r) * KVD + kvh * HD + c]);
            float4 vv = *(const float4*)(&g_v[(size_t)(kb * 128 + r) * KVD + kvh * HD + c]);
            uint32_t* dk = &Ks[r * AS + c];
            dk[0] = f2tf(kv.x); dk[1] = f2tf(kv.y); dk[2] = f2tf(kv.z); dk[3] = f2tf(kv.w);
            uint32_t* dv = &Vs[r * AS + c];
            dv[0] = f2tf(vv.x); dv[1] = f2tf(vv.y); dv[2] = f2tf(vv.z); dv[3] = f2tf(vv.w);
        }
        __syncthreads();

        // scores = Q @ K^T for this warp's 16 rows x 128 cols
        float s[16][4];
#pragma unroll
        for (int i = 0; i < 16; i++)
#pragma unroll
            for (int j = 0; j < 4; j++) s[i][j] = 0.f;

#pragma unroll 4
        for (int ks = 0; ks < 16; ++ks) {
            const int kk = ks * 8;
            uint32_t a0 = Qs[(wr + gid)     * AS + kk + tig];
            uint32_t a1 = Qs[(wr + gid + 8) * AS + kk + tig];
            uint32_t a2 = Qs[(wr + gid)     * AS + kk + tig + 4];
            uint32_t a3 = Qs[(wr + gid + 8) * AS + kk + tig + 4];
#pragma unroll
            for (int nt = 0; nt < 16; ++nt) {
                const int n0 = nt * 8;
                uint32_t b0 = Ks[(n0 + gid) * AS + kk + tig];
                uint32_t b1 = Ks[(n0 + gid) * AS + kk + tig + 4];
                mma_tf32(s[nt], a0, a1, a2, a3, b0, b1);
            }
        }
        __syncthreads();  // all warps done reading Ks before it becomes Ps

        const float scale = 0.08838834764831845f;  // 1/sqrt(128)
        if (kb == qb) {
            const int r1 = wr + gid, r2 = r1 + 8;  // local row == local col space on diagonal
#pragma unroll
            for (int nt = 0; nt < 16; ++nt) {
                int c0 = nt * 8 + tig * 2;
                s[nt][0] = (c0     <= r1) ? s[nt][0] * scale : -1e30f;
                s[nt][1] = (c0 + 1 <= r1) ? s[nt][1] * scale : -1e30f;
                s[nt][2] = (c0     <= r2) ? s[nt][2] * scale : -1e30f;
                s[nt][3] = (c0 + 1 <= r2) ? s[nt][3] * scale : -1e30f;
            }
        } else {
#pragma unroll
            for (int nt = 0; nt < 16; ++nt) {
                s[nt][0] *= scale; s[nt][1] *= scale;
                s[nt][2] *= scale; s[nt][3] *= scale;
            }
        }

        // online softmax (rows r1 = wr+gid, r2 = r1+8)
        float mx1 = -1e30f, mx2 = -1e30f;
#pragma unroll
        for (int nt = 0; nt < 16; ++nt) {
            mx1 = fmaxf(mx1, fmaxf(s[nt][0], s[nt][1]));
            mx2 = fmaxf(mx2, fmaxf(s[nt][2], s[nt][3]));
        }
        mx1 = fmaxf(mx1, __shfl_xor_sync(0xffffffffu, mx1, 1));
        mx1 = fmaxf(mx1, __shfl_xor_sync(0xffffffffu, mx1, 2));
        mx2 = fmaxf(mx2, __shfl_xor_sync(0xffffffffu, mx2, 1));
        mx2 = fmaxf(mx2, __shfl_xor_sync(0xffffffffu, mx2, 2));

        float nm1 = fmaxf(m1, mx1), nm2 = fmaxf(m2, mx2);
        float al1 = __expf(m1 - nm1), al2 = __expf(m2 - nm2);
        float sum1 = 0.f, sum2 = 0.f;
#pragma unroll
        for (int nt = 0; nt < 16; ++nt) {
            s[nt][0] = __expf(s[nt][0] - nm1); sum1 += s[nt][0];
            s[nt][1] = __expf(s[nt][1] - nm1); sum1 += s[nt][1];
            s[nt][2] = __expf(s[nt][2] - nm2); sum2 += s[nt][2];
            s[nt][3] = __expf(s[nt][3] - nm2); sum2 += s[nt][3];
        }
        sum1 += __shfl_xor_sync(0xffffffffu, sum1, 1);
        sum1 += __shfl_xor_sync(0xffffffffu, sum1, 2);
        sum2 += __shfl_xor_sync(0xffffffffu, sum2, 1);
        sum2 += __shfl_xor_sync(0xffffffffu, sum2, 2);

        l1 = l1 * al1 + sum1; m1 = nm1;
        l2 = l2 * al2 + sum2; m2 = nm2;
#pragma unroll
        for (int nt = 0; nt < 16; ++nt) {
            o[nt][0] *= al1; o[nt][1] *= al1;
            o[nt][2] *= al2; o[nt][3] *= al2;
        }

        // write P into Ks (each warp writes only its own 16 rows)
#pragma unroll
        for (int nt = 0; nt < 16; ++nt) {
            int c0 = nt * 8 + tig * 2;
            uint32_t* p1 = &Ks[(wr + gid) * AS + c0];
            p1[0] = f2tf(s[nt][0]); p1[1] = f2tf(s[nt][1]);
            uint32_t* p2 = &Ks[(wr + gid + 8) * AS + c0];
            p2[0] = f2tf(s[nt][2]); p2[1] = f2tf(s[nt][3]);
        }
        __syncwarp();

        // o += P @ V
#pragma unroll 4
        for (int ks = 0; ks < 16; ++ks) {
            const int kk = ks * 8;
            uint32_t a0 = Ks[(wr + gid)     * AS + kk + tig];
            uint32_t a1 = Ks[(wr + gid + 8) * AS + kk + tig];
            uint32_t a2 = Ks[(wr + gid)     * AS + kk + tig + 4];
            uint32_t a3 = Ks[(wr + gid + 8) * AS + kk + tig + 4];
#pragma unroll
            for (int nt = 0; nt < 16; ++nt) {
                const int n0 = nt * 8;
                uint32_t b0 = Vs[(kk + tig)     * AS + n0 + gid];
                uint32_t b1 = Vs[(kk + tig + 4) * AS + n0 + gid];
                mma_tf32(o[nt], a0, a1, a2, a3, b0, b1);
            }
        }
    }

    const float inv1 = 1.f / l1, inv2 = 1.f / l2;
    const int r1 = q0 + wr + gid;
#pragma unroll
    for (int nt = 0; nt < 16; ++nt) {
        int c = h * HD + nt * 8 + tig * 2;
        *(float2*)&g_attn[(size_t)r1 * DIM + c] =
            make_float2(o[nt][0] * inv1, o[nt][1] * inv1);
        *(float2*)&g_attn[(size_t)(r1 + 8) * DIM + c] =
            make_float2(o[nt][2] * inv2, o[nt][3] * inv2);
    }
}

// ---------------------------------------------------------------------------
extern "C" void kernel_launch(void* const* d_in, const int* in_sizes, int n_in,
                              void* d_out, int out_size) {
    (void)in_sizes; (void)n_in; (void)out_size;
    const float* x  = (const float*)d_in[0];
    const float* wq = (const float*)d_in[1];
    const float* wk = (const float*)d_in[2];
    const float* wv = (const float*)d_in[3];
    const float* wo = (const float*)d_in[4];
    float* out = (float*)d_out;

    float *q, *k, *v, *attn;
    cudaGetSymbolAddress((void**)&q, g_q);
    cudaGetSymbolAddress((void**)&k, g_k);
    cudaGetSymbolAddress((void**)&v, g_v);
    cudaGetSymbolAddress((void**)&attn, g_attn);

    cudaFuncSetAttribute(gemm_nt_tf32, cudaFuncAttributeMaxDynamicSharedMemorySize, GEMM_SMEM);
    cudaFuncSetAttribute(attn_kernel, cudaFuncAttributeMaxDynamicSharedMemorySize, ATTN_SMEM);

    // Projections
    gemm_nt_tf32<<<dim3(DIM / 128, SEQ / 128), 256, GEMM_SMEM>>>(x, wq, q, DIM, DIM);
    gemm_nt_tf32<<<dim3(KVD / 128, SEQ / 128), 256, GEMM_SMEM>>>(x, wk, k, KVD, DIM);
    gemm_nt_tf32<<<dim3(KVD / 128, SEQ / 128), 256, GEMM_SMEM>>>(x, wv, v, KVD, DIM);

    // RoPE on q and k
    rope_kernel<<<(SEQ * NH * 64) / 256, 256>>>(q, NH);
    rope_kernel<<<(SEQ * NKV * 64) / 256, 256>>>(k, NKV);

    // Attention
    attn_kernel<<<dim3(SEQ / 128, NH), 256, ATTN_SMEM>>>();

    // Output projection straight into d_out
    gemm_nt_tf32<<<dim3(DIM / 128, SEQ / 128), 256, GEMM_SMEM>>>(attn, wo, out, DIM, DIM);
}